// round 2
// baseline (speedup 1.0000x reference)
#include <cuda_runtime.h>

#define T_SEQ 2048
#define NBATCH 64
#define NIN 16
#define NHEAD 8
#define HID 64

typedef unsigned long long u64;

// h history scratch: (T, B, H, HID) fp32 = 256 MB (device global; no runtime allocs)
__device__ float g_hist[(size_t)T_SEQ * NBATCH * NHEAD * HID];

// ---- packed fp32x2 helpers (Blackwell fma.rn.f32x2: two independent rn FMAs) ----
__device__ __forceinline__ u64 ffma2(u64 a, u64 b, u64 c) {
    u64 d;
    asm("fma.rn.f32x2 %0, %1, %2, %3;" : "=l"(d) : "l"(a), "l"(b), "l"(c));
    return d;
}
__device__ __forceinline__ u64 pack2(float lo, float hi) {
    u64 u; asm("mov.b64 %0, {%1, %2};" : "=l"(u) : "f"(lo), "f"(hi)); return u;
}
__device__ __forceinline__ float2 unpack2(u64 u) {
    float2 f; asm("mov.b64 {%0, %1}, %2;" : "=f"(f.x), "=f"(f.y) : "l"(u)); return f;
}
__device__ __forceinline__ float sigf(float z) {
    return __fdividef(1.0f, 1.0f + __expf(-z));
}
__device__ __forceinline__ float tanhf_fast(float z) {
    // tanh(z) = 2*sigmoid(2z) - 1; abs err ~1e-7, fine vs 1e-3 tolerance
    return fmaf(2.0f, sigf(2.0f * z), -1.0f);
}

// ============================================================================
// Recurrent kernel.
// Grid: 256 CTAs = head (8) x batch-pair (32). Block: 128 threads.
// Thread t owns gate rows ga = t (i|f) and gb = t+128 (g|o), for 2 batches.
// Weights live in registers packed as f32x2 over the k dimension.
// ============================================================================
__global__ __launch_bounds__(128, 2) void lstm_rec_kernel(
    const float* __restrict__ x,     // (T, B, 16)
    const float* __restrict__ W_ih,  // (8, 256, 16)
    const float* __restrict__ W_hh,  // (8, 256, 64)
    const float* __restrict__ b_ih,  // (8, 256)
    const float* __restrict__ b_hh)  // (8, 256)
{
    const int tid  = threadIdx.x;
    const int head = blockIdx.x >> 5;
    const int b0   = (blockIdx.x & 31) * 2;   // batches b0, b0+1

    const int ga = tid;         // gate row in [0,128): i (tid<64) or f (tid>=64)
    const int gb = tid + 128;   // gate row in [128,256): g (tid<64) or o (tid>=64)

    // ---- load weights into registers, packed over k pairs ----
    u64 whA[32], whB[32], wiA[8], wiB[8];
    {
        const u64* p = reinterpret_cast<const u64*>(W_hh + (head * 256 + ga) * HID);
#pragma unroll
        for (int j = 0; j < 32; ++j) whA[j] = p[j];
        p = reinterpret_cast<const u64*>(W_hh + (head * 256 + gb) * HID);
#pragma unroll
        for (int j = 0; j < 32; ++j) whB[j] = p[j];
        p = reinterpret_cast<const u64*>(W_ih + (head * 256 + ga) * NIN);
#pragma unroll
        for (int j = 0; j < 8; ++j) wiA[j] = p[j];
        p = reinterpret_cast<const u64*>(W_ih + (head * 256 + gb) * NIN);
#pragma unroll
        for (int j = 0; j < 8; ++j) wiB[j] = p[j];
    }
    const float biasA = b_ih[head * 256 + ga] + b_hh[head * 256 + ga];
    const float biasB = b_ih[head * 256 + gb] + b_hh[head * 256 + gb];

    __shared__ __align__(8) float hsb[2][HID];   // h state per batch (contiguous for LDS.64 pairs)
    __shared__ __align__(8) float xs[32];        // x[t, b0, :] ++ x[t, b0+1, :]
    __shared__ float zex[2][2][64];              // [batch][0=f,1=o][j] exchange

    if (tid < 64) hsb[0][tid] = 0.0f; else hsb[1][tid - 64] = 0.0f;
    float c0 = 0.0f, c1 = 0.0f;

    const float* xrow = x + b0 * NIN;

    for (int ts = 0; ts < T_SEQ; ++ts) {
        // b0 and b0+1 rows of x are 32 contiguous floats
        if (tid < 32) xs[tid] = xrow[ts * (NBATCH * NIN) + tid];
        __syncthreads();   // xs ready; h_{t-1} in hsb visible

        u64 aA0 = pack2(biasA, 0.0f); u64 aA1 = aA0;
        u64 aB0 = pack2(biasB, 0.0f); u64 aB1 = aB0;

        // input projection (8 k-pairs)
        const u64* xu = reinterpret_cast<const u64*>(xs);
#pragma unroll
        for (int j = 0; j < 8; ++j) {
            u64 x0 = xu[j], x1 = xu[8 + j];
            aA0 = ffma2(wiA[j], x0, aA0);
            aA1 = ffma2(wiA[j], x1, aA1);
            aB0 = ffma2(wiB[j], x0, aB0);
            aB1 = ffma2(wiB[j], x1, aB1);
        }
        // recurrent projection (32 k-pairs)
        const u64* hu0 = reinterpret_cast<const u64*>(hsb[0]);
        const u64* hu1 = reinterpret_cast<const u64*>(hsb[1]);
#pragma unroll
        for (int j = 0; j < 32; ++j) {
            u64 h0 = hu0[j], h1 = hu1[j];
            aA0 = ffma2(whA[j], h0, aA0);
            aA1 = ffma2(whA[j], h1, aA1);
            aB0 = ffma2(whB[j], h0, aB0);
            aB1 = ffma2(whB[j], h1, aB1);
        }
        float2 fA0 = unpack2(aA0), fA1 = unpack2(aA1);
        float2 fB0 = unpack2(aB0), fB1 = unpack2(aB1);
        float zA0 = fA0.x + fA0.y, zA1 = fA1.x + fA1.y;
        float zB0 = fB0.x + fB0.y, zB1 = fB1.x + fB1.y;

        if (tid >= 64) {   // publish f and o gate pre-activations
            int j = tid - 64;
            zex[0][0][j] = zA0; zex[1][0][j] = zA1;   // f
            zex[0][1][j] = zB0; zex[1][1][j] = zB1;   // o
        }
        __syncthreads();   // zex ready; all hsb reads complete

        if (tid < 64) {    // owns i (zA) and g (zB); cell state update
            int j = tid;
            float i0 = sigf(zA0),           g0 = tanhf_fast(zB0);
            float f0 = sigf(zex[0][0][j]),  o0 = sigf(zex[0][1][j]);
            c0 = fmaf(f0, c0, i0 * g0);
            float h0 = o0 * tanhf_fast(c0);

            float i1 = sigf(zA1),           g1 = tanhf_fast(zB1);
            float f1 = sigf(zex[1][0][j]),  o1 = sigf(zex[1][1][j]);
            c1 = fmaf(f1, c1, i1 * g1);
            float h1 = o1 * tanhf_fast(c1);

            hsb[0][j] = h0;
            hsb[1][j] = h1;
            int base = ((ts * NBATCH + b0) * NHEAD + head) * HID + j;
            g_hist[base] = h0;
            g_hist[base + NHEAD * HID] = h1;
        }
        // loop-top __syncthreads publishes new hsb for step ts+1
    }
}

// ============================================================================
// Epilogue: out[t,b,h] = dot(h[t,b,h,:], W_lin[h,:]) + b_lin[h]
//           lstm_out[t,b,j] = sum_h h[t,b,h,j]
// One block per (t,b); memory-bound (268 MB read).
// ============================================================================
__global__ void lstm_epi_kernel(
    const float* __restrict__ W_lin,   // (8, 64)
    const float* __restrict__ b_lin,   // (8,)
    float* __restrict__ out,           // (T, B, 8)
    float* __restrict__ lstm_out)      // (T, B, 64)
{
    const int tb = blockIdx.x;          // t*64 + b
    const int j  = threadIdx.x;         // 0..63
    const int base = tb * (NHEAD * HID);

    float v[NHEAD];
    float acc = 0.0f;
#pragma unroll
    for (int h = 0; h < NHEAD; ++h) {
        v[h] = g_hist[base + h * HID + j];
        acc += v[h];
    }
    lstm_out[tb * HID + j] = acc;

#pragma unroll
    for (int h = 0; h < NHEAD; ++h) v[h] *= W_lin[h * HID + j];
#pragma unroll
    for (int h = 0; h < NHEAD; ++h) {
#pragma unroll
        for (int off = 16; off > 0; off >>= 1)
            v[h] += __shfl_down_sync(0xFFFFFFFFu, v[h], off);
    }
    __shared__ float part[2][NHEAD];
    if ((j & 31) == 0) {
        int w = j >> 5;
#pragma unroll
        for (int h = 0; h < NHEAD; ++h) part[w][h] = v[h];
    }
    __syncthreads();
    if (j < NHEAD)
        out[tb * NHEAD + j] = part[0][j] + part[1][j] + b_lin[j];
}

extern "C" void kernel_launch(void* const* d_in, const int* in_sizes, int n_in,
                              void* d_out, int out_size) {
    const float* x     = (const float*)d_in[0];
    const float* W_ih  = (const float*)d_in[1];
    const float* W_hh  = (const float*)d_in[2];
    const float* b_ih  = (const float*)d_in[3];
    const float* b_hh  = (const float*)d_in[4];
    const float* W_lin = (const float*)d_in[5];
    const float* b_lin = (const float*)d_in[6];

    float* out      = (float*)d_out;                       // (T,B,H) first
    float* lstm_out = out + (size_t)T_SEQ * NBATCH * NHEAD; // then (T,B,HID)

    lstm_rec_kernel<<<NHEAD * (NBATCH / 2), 128>>>(x, W_ih, W_hh, b_ih, b_hh);
    lstm_epi_kernel<<<T_SEQ * NBATCH, 64>>>(W_lin, b_lin, out, lstm_out);
}

// round 3
// speedup vs baseline: 1.0238x; 1.0238x over previous
#include <cuda_runtime.h>

#define T_SEQ 2048
#define NBATCH 64
#define NIN 16
#define NHEAD 8
#define HID 64

typedef unsigned long long u64;

// h history scratch: (T, B, H, HID) fp32 = 256 MB (device global; no runtime allocs)
__device__ float g_hist[(size_t)T_SEQ * NBATCH * NHEAD * HID];

// ---- packed fp32x2 helpers (Blackwell fma.rn.f32x2: two independent rn FMAs) ----
__device__ __forceinline__ u64 ffma2(u64 a, u64 b, u64 c) {
    u64 d;
    asm("fma.rn.f32x2 %0, %1, %2, %3;" : "=l"(d) : "l"(a), "l"(b), "l"(c));
    return d;
}
__device__ __forceinline__ u64 pack2(float lo, float hi) {
    u64 u; asm("mov.b64 %0, {%1, %2};" : "=l"(u) : "f"(lo), "f"(hi)); return u;
}
__device__ __forceinline__ float2 unpack2(u64 u) {
    float2 f; asm("mov.b64 {%0, %1}, %2;" : "=f"(f.x), "=f"(f.y) : "l"(u)); return f;
}
__device__ __forceinline__ float sigf(float z) {
    return __fdividef(1.0f, 1.0f + __expf(-z));
}
__device__ __forceinline__ float tanhf_fast(float z) {
    // tanh(z) = 2*sigmoid(2z) - 1
    return fmaf(2.0f, sigf(2.0f * z), -1.0f);
}

// ============================================================================
// Recurrent kernel.
// Grid: 256 CTAs = head (8) x batch-pair (32). Block: 256 threads.
// Thread t owns ONE gate row r=t (gate = t>>6: 0=i,1=f,2=g,3=o; j = t&63)
// for BOTH batches of the pair (2 independent f32x2 accumulator chains).
// Weights register-resident, packed f32x2 over k (80 regs/thread).
// After the z-exchange, threads t<128 each own one (batch, j) cell and do
// all activations + cell update (MUFU spread over warps 0-3 -> all SMSPs).
// Threads 248-255 are the x-prefetch crew (double-buffered xs in smem).
// ============================================================================
__global__ __launch_bounds__(256, 2) void lstm_rec_kernel(
    const float* __restrict__ x,     // (T, B, 16)
    const float* __restrict__ W_ih,  // (8, 256, 16)
    const float* __restrict__ W_hh,  // (8, 256, 64)
    const float* __restrict__ b_ih,  // (8, 256)
    const float* __restrict__ b_hh)  // (8, 256)
{
    const int t    = threadIdx.x;
    const int head = blockIdx.x >> 5;
    const int b0   = (blockIdx.x & 31) * 2;   // batches b0, b0+1

    // ---- weights into registers, f32x2-packed over k ----
    u64 wh[32], wi[8];
    {
        const ulonglong2* p = reinterpret_cast<const ulonglong2*>(W_hh + (head * 256 + t) * HID);
#pragma unroll
        for (int k = 0; k < 16; ++k) { ulonglong2 v = p[k]; wh[2 * k] = v.x; wh[2 * k + 1] = v.y; }
        const ulonglong2* q = reinterpret_cast<const ulonglong2*>(W_ih + (head * 256 + t) * NIN);
#pragma unroll
        for (int k = 0; k < 4; ++k) { ulonglong2 v = q[k]; wi[2 * k] = v.x; wi[2 * k + 1] = v.y; }
    }
    const float bias = b_ih[head * 256 + t] + b_hh[head * 256 + t];

    __shared__ __align__(16) float hsb[2][HID];       // h state per batch
    __shared__ __align__(16) float xs[2][2][NIN];     // double-buffered x rows (2 batches)
    __shared__ __align__(8)  float zbuf[4][64][2];    // [gate][j][batch] pre-activations

    if (t < 128) { reinterpret_cast<float*>(hsb)[t] = 0.0f; }

    // x prefetch crew: 8 threads cover 32 contiguous floats (b0 and b0+1 rows)
    const float* xbase = x + (size_t)b0 * NIN;        // + ts * (NBATCH*NIN)
    float4 xr;
    if (t >= 248) {
        int idx = t - 248;
        xr = reinterpret_cast<const float4*>(xbase)[idx];                      // ts = 0
        reinterpret_cast<float4*>(&xs[0][0][0])[idx] = xr;
        xr = reinterpret_cast<const float4*>(xbase + (size_t)NBATCH * NIN)[idx]; // ts = 1
    }

    const int bloc = (t >> 6) & 1;   // consumer's batch (t < 128)
    const int jj   = t & 63;         // consumer's hidden index
    float c = 0.0f;                  // consumer-owned cell state

    for (int ts = 0; ts < T_SEQ; ++ts) {
        __syncthreads();             // h(ts-1) and xs[ts&1] visible
        const int cur = ts & 1;

        u64 a0 = pack2(bias, 0.0f);
        u64 a1 = a0;

        // input projection (16 MACs/batch as 8 ffma2)
        const ulonglong2* xu0 = reinterpret_cast<const ulonglong2*>(&xs[cur][0][0]);
        const ulonglong2* xu1 = reinterpret_cast<const ulonglong2*>(&xs[cur][1][0]);
#pragma unroll
        for (int k = 0; k < 4; ++k) {
            ulonglong2 p0 = xu0[k], p1 = xu1[k];
            a0 = ffma2(wi[2 * k], p0.x, a0);
            a1 = ffma2(wi[2 * k], p1.x, a1);
            a0 = ffma2(wi[2 * k + 1], p0.y, a0);
            a1 = ffma2(wi[2 * k + 1], p1.y, a1);
        }
        // recurrent projection (64 MACs/batch as 32 ffma2)
        const ulonglong2* h0 = reinterpret_cast<const ulonglong2*>(&hsb[0][0]);
        const ulonglong2* h1 = reinterpret_cast<const ulonglong2*>(&hsb[1][0]);
#pragma unroll
        for (int k = 0; k < 16; ++k) {
            ulonglong2 p0 = h0[k], p1 = h1[k];
            a0 = ffma2(wh[2 * k], p0.x, a0);
            a1 = ffma2(wh[2 * k], p1.x, a1);
            a0 = ffma2(wh[2 * k + 1], p0.y, a0);
            a1 = ffma2(wh[2 * k + 1], p1.y, a1);
        }
        float2 f0 = unpack2(a0), f1 = unpack2(a1);
        float z0 = f0.x + f0.y, z1 = f1.x + f1.y;
        *reinterpret_cast<float2*>(&zbuf[t >> 6][t & 63][0]) = make_float2(z0, z1);

        // crew: publish x(ts+1) into the other buffer, start LDG for x(ts+2)
        if (t >= 248) {
            int idx = t - 248;
            reinterpret_cast<float4*>(&xs[cur ^ 1][0][0])[idx] = xr;
            int tn = (ts + 2 < T_SEQ) ? ts + 2 : T_SEQ - 1;
            xr = reinterpret_cast<const float4*>(xbase + (size_t)tn * NBATCH * NIN)[idx];
        }

        __syncthreads();             // zbuf + xs[next] visible

        if (t < 128) {               // one (batch, j) cell per thread
            float zi = zbuf[0][jj][bloc];
            float zf = zbuf[1][jj][bloc];
            float zg = zbuf[2][jj][bloc];
            float zo = zbuf[3][jj][bloc];
            float iv = sigf(zi);
            float fv = sigf(zf);
            float gv = tanhf_fast(zg);
            float ov = sigf(zo);
            c = fmaf(fv, c, iv * gv);
            float h = ov * tanhf_fast(c);
            hsb[bloc][jj] = h;
            g_hist[(((size_t)ts * NBATCH + b0 + bloc) * NHEAD + head) * HID + jj] = h;
        }
        // loop-top barrier publishes new h for step ts+1
    }
}

// ============================================================================
// Epilogue: out[t,b,h] = dot(h[t,b,h,:], W_lin[h,:]) + b_lin[h]
//           lstm_out[t,b,j] = sum_h h[t,b,h,j]
// float4 / high-MLP version: 16 threads per (t,b) cell, 8 LDG.128 in flight.
// ============================================================================
__global__ __launch_bounds__(256) void lstm_epi_kernel(
    const float* __restrict__ W_lin,   // (8, 64)
    const float* __restrict__ b_lin,   // (8,)
    float* __restrict__ out,           // (T, B, 8)
    float* __restrict__ lstm_out)      // (T, B, 64)
{
    const int cell = blockIdx.x * 16 + (threadIdx.x >> 4);   // t*NBATCH + b
    const int q    = threadIdx.x & 15;                        // j-quad index

    const float4* hist4 = reinterpret_cast<const float4*>(g_hist) + (size_t)cell * 128;
    float4 v[NHEAD];
#pragma unroll
    for (int h = 0; h < NHEAD; ++h) v[h] = hist4[h * 16 + q];

    float4 s = v[0];
#pragma unroll
    for (int h = 1; h < NHEAD; ++h) {
        s.x += v[h].x; s.y += v[h].y; s.z += v[h].z; s.w += v[h].w;
    }
    reinterpret_cast<float4*>(lstm_out)[(size_t)cell * 16 + q] = s;

    const float4* wl4 = reinterpret_cast<const float4*>(W_lin);
    float d[NHEAD];
#pragma unroll
    for (int h = 0; h < NHEAD; ++h) {
        float4 w = wl4[h * 16 + q];
        float acc = v[h].x * w.x;
        acc = fmaf(v[h].y, w.y, acc);
        acc = fmaf(v[h].z, w.z, acc);
        acc = fmaf(v[h].w, w.w, acc);
        d[h] = acc;
    }
#pragma unroll
    for (int off = 8; off > 0; off >>= 1) {
#pragma unroll
        for (int h = 0; h < NHEAD; ++h)
            d[h] += __shfl_xor_sync(0xFFFFFFFFu, d[h], off);
    }
    if (q == 0) {
#pragma unroll
        for (int h = 0; h < NHEAD; ++h)
            out[(size_t)cell * NHEAD + h] = d[h] + b_lin[h];
    }
}

extern "C" void kernel_launch(void* const* d_in, const int* in_sizes, int n_in,
                              void* d_out, int out_size) {
    const float* x     = (const float*)d_in[0];
    const float* W_ih  = (const float*)d_in[1];
    const float* W_hh  = (const float*)d_in[2];
    const float* b_ih  = (const float*)d_in[3];
    const float* b_hh  = (const float*)d_in[4];
    const float* W_lin = (const float*)d_in[5];
    const float* b_lin = (const float*)d_in[6];

    float* out      = (float*)d_out;                        // (T,B,H) first
    float* lstm_out = out + (size_t)T_SEQ * NBATCH * NHEAD; // then (T,B,HID)

    lstm_rec_kernel<<<NHEAD * (NBATCH / 2), 256>>>(x, W_ih, W_hh, b_ih, b_hh);
    lstm_epi_kernel<<<(T_SEQ * NBATCH) / 16, 256>>>(W_lin, b_lin, out, lstm_out);
}